// round 2
// baseline (speedup 1.0000x reference)
#include <cuda_runtime.h>
#include <math.h>

#define TT 2048      // tokens
#define HH 2048      // hidden
#define II 1024      // moe intermediate
#define EE 32        // routed experts
#define TOPK 4
#define NROUTED (TT*TOPK)       // 8192
#define NPAIRS  (NROUTED + TT)  // 10240 (routed pairs + shared-expert rows)

// ---------------- device scratch (static: no allocation allowed) ----------------
__device__ int   g_counts[EE];
__device__ int   g_cursor[EE];
__device__ int   g_offsets[EE];
__device__ int   g_topk_idx[NROUTED];
__device__ float g_topk_w[NROUTED];
__device__ int   g_pair_token[NROUTED];   // pos -> token
__device__ int   g_pair_pos[NROUTED];     // t*4+j -> pos
__device__ float g_act[(size_t)NPAIRS * II];       // ~42 MB
__device__ float g_pairout[(size_t)NPAIRS * HH];   // ~84 MB

// ---------------- misc small kernels ----------------
__global__ void zero_kernel() {
    int i = threadIdx.x;
    if (i < EE) { g_counts[i] = 0; g_cursor[i] = 0; }
}

__global__ void offsets_kernel() {
    if (threadIdx.x == 0) {
        int s = 0;
        for (int e = 0; e < EE; ++e) { g_offsets[e] = s; s += g_counts[e]; }
    }
}

__global__ void scatter_kernel() {
    int t = blockIdx.x * blockDim.x + threadIdx.x;
    if (t >= TT) return;
    #pragma unroll
    for (int j = 0; j < TOPK; ++j) {
        int e = g_topk_idx[t*TOPK + j];
        int pos = g_offsets[e] + atomicAdd(&g_cursor[e], 1);
        g_pair_token[pos] = t;
        g_pair_pos[t*TOPK + j] = pos;
    }
}

// ---------------- gate + routing: 4 tokens per block ----------------
__global__ __launch_bounds__(256) void gate_kernel(
        const float* __restrict__ x,
        const float* __restrict__ gw,
        const float* __restrict__ bias)
{
    __shared__ float xs[4][HH];
    __shared__ float logits_s[4][EE];
    __shared__ float bias_s[EE];

    int tid = threadIdx.x;
    int t0  = blockIdx.x * 4;

    // load 4 token rows (4*2048 floats = 2048 float4)
    const float4* xg  = (const float4*)(x + (size_t)t0 * HH);
    float4*       xs4 = (float4*)&xs[0][0];
    #pragma unroll
    for (int i = 0; i < 8; ++i) xs4[tid + i*256] = xg[tid + i*256];
    if (tid < EE) bias_s[tid] = bias[tid];
    __syncthreads();

    int warp = tid >> 5, lane = tid & 31;

    // 8 warps x 4 experts each, 4 tokens per dot
    #pragma unroll
    for (int ei = 0; ei < 4; ++ei) {
        int e = warp*4 + ei;
        const float* gr = gw + (size_t)e * HH;
        float a0=0.f, a1=0.f, a2=0.f, a3=0.f;
        for (int h = lane; h < HH; h += 32) {
            float g = gr[h];
            a0 = fmaf(g, xs[0][h], a0);
            a1 = fmaf(g, xs[1][h], a1);
            a2 = fmaf(g, xs[2][h], a2);
            a3 = fmaf(g, xs[3][h], a3);
        }
        #pragma unroll
        for (int off = 16; off; off >>= 1) {
            a0 += __shfl_xor_sync(0xffffffffu, a0, off);
            a1 += __shfl_xor_sync(0xffffffffu, a1, off);
            a2 += __shfl_xor_sync(0xffffffffu, a2, off);
            a3 += __shfl_xor_sync(0xffffffffu, a3, off);
        }
        if (lane == 0) {
            logits_s[0][e] = a0; logits_s[1][e] = a1;
            logits_s[2][e] = a2; logits_s[3][e] = a3;
        }
    }
    __syncthreads();

    // warps 0..3: routing for token t0+warp, lane = expert
    if (warp < 4) {
        int t = t0 + warp;
        float logit = logits_s[warp][lane];
        float s   = 1.f / (1.f + expf(-logit));     // sigmoid score
        float sfc = s + bias_s[lane];               // biased score for choice

        // --- group score: sum of top-2 within each 8-lane group ---
        float m1 = sfc, m2 = -INFINITY;
        #pragma unroll
        for (int off = 4; off >= 1; off >>= 1) {    // xor 4,2,1 stays inside 8-lane group
            float o1 = __shfl_xor_sync(0xffffffffu, m1, off);
            float o2 = __shfl_xor_sync(0xffffffffu, m2, off);
            float hi = fmaxf(m1, o1);
            float lo = fmaxf(fminf(m1, o1), fmaxf(m2, o2));
            m1 = hi; m2 = lo;
        }
        float gs = m1 + m2;
        float gv[4];
        gv[0] = __shfl_sync(0xffffffffu, gs, 0);
        gv[1] = __shfl_sync(0xffffffffu, gs, 8);
        gv[2] = __shfl_sync(0xffffffffu, gs, 16);
        gv[3] = __shfl_sync(0xffffffffu, gs, 24);

        // top-2 groups (strict >, so ties keep lower index == lax.top_k)
        int b1 = 0; float v1 = gv[0];
        #pragma unroll
        for (int gg = 1; gg < 4; ++gg) if (gv[gg] > v1) { v1 = gv[gg]; b1 = gg; }
        int b2 = -1; float v2 = -INFINITY;
        #pragma unroll
        for (int gg = 0; gg < 4; ++gg) {
            if (gg == b1) continue;
            if (gv[gg] > v2) { v2 = gv[gg]; b2 = gg; }
        }

        int mygrp = lane >> 3;
        float val = (mygrp == b1 || mygrp == b2) ? sfc : 0.0f;  // match jnp.where(...,0.0)

        // --- top-4 experts on masked biased scores (lower-index tiebreak) ---
        int   sel_i[TOPK];
        float sel_w[TOPK];
        float cur = val;
        #pragma unroll
        for (int j = 0; j < TOPK; ++j) {
            float bv = cur; int bi = lane;
            #pragma unroll
            for (int off = 16; off >= 1; off >>= 1) {
                float ov = __shfl_xor_sync(0xffffffffu, bv, off);
                int   oi = __shfl_xor_sync(0xffffffffu, bi, off);
                if (ov > bv || (ov == bv && oi < bi)) { bv = ov; bi = oi; }
            }
            sel_i[j] = bi;
            sel_w[j] = __shfl_sync(0xffffffffu, s, bi);  // UNbiased sigmoid score
            if (lane == bi) cur = -INFINITY;
        }
        if (lane == 0) {
            float sum = sel_w[0] + sel_w[1] + sel_w[2] + sel_w[3];
            float scale = 2.5f / (sum + 1e-20f);
            #pragma unroll
            for (int j = 0; j < TOPK; ++j) {
                g_topk_idx[t*TOPK + j] = sel_i[j];
                g_topk_w[t*TOPK + j]   = sel_w[j] * scale;
                atomicAdd(&g_counts[sel_i[j]], 1);
            }
        }
    }
}

// ---------------- phase A: act = silu(X W1^T) * (X W3^T), expert-gathered ----------------
// grid: (II/64, EE+1, 32) ; block 256
__global__ __launch_bounds__(256) void phaseA_kernel(
        const float* __restrict__ x,
        const float* __restrict__ w1,
        const float* __restrict__ w3,
        const float* __restrict__ ws1,
        const float* __restrict__ ws3)
{
    const int g = blockIdx.y;
    int m_count, base_pos;
    const float *W1, *W3;
    if (g < EE) {
        m_count = g_counts[g]; base_pos = g_offsets[g];
        W1 = w1 + (size_t)g * II * HH; W3 = w3 + (size_t)g * II * HH;
    } else {
        m_count = TT; base_pos = NROUTED; W1 = ws1; W3 = ws3;
    }
    const int mtile = blockIdx.z;
    if (mtile * 64 >= m_count) return;
    const int rows = min(64, m_count - mtile * 64);
    const int n0 = blockIdx.x * 64;

    __shared__ float As [16][64];
    __shared__ float B1s[16][64];
    __shared__ float B3s[16][64];
    __shared__ int   toks[64];

    const int tid = threadIdx.x;
    if (tid < 64) {
        int r = min(tid, rows - 1);
        toks[tid] = (g < EE) ? g_pair_token[base_pos + mtile*64 + r] : (mtile*64 + tid);
    }
    __syncthreads();

    const int tx = tid & 15, ty = tid >> 4;
    float c1[4][4] = {{0}}, c3[4][4] = {{0}};

    const int lr = tid >> 2;          // 0..63
    const int lk = (tid & 3) * 4;     // 0,4,8,12
    const float* arow  = x  + (size_t)toks[lr] * HH;
    const float* b1row = W1 + (size_t)(n0 + lr) * HH;
    const float* b3row = W3 + (size_t)(n0 + lr) * HH;

    for (int k0 = 0; k0 < HH; k0 += 16) {
        float4 av  = *(const float4*)(arow  + k0 + lk);
        float4 b1v = *(const float4*)(b1row + k0 + lk);
        float4 b3v = *(const float4*)(b3row + k0 + lk);
        __syncthreads();
        As [lk+0][lr]=av.x;  As [lk+1][lr]=av.y;  As [lk+2][lr]=av.z;  As [lk+3][lr]=av.w;
        B1s[lk+0][lr]=b1v.x; B1s[lk+1][lr]=b1v.y; B1s[lk+2][lr]=b1v.z; B1s[lk+3][lr]=b1v.w;
        B3s[lk+0][lr]=b3v.x; B3s[lk+1][lr]=b3v.y; B3s[lk+2][lr]=b3v.z; B3s[lk+3][lr]=b3v.w;
        __syncthreads();
        #pragma unroll
        for (int kk = 0; kk < 16; ++kk) {
            float4 a  = *(const float4*)&As [kk][ty*4];
            float4 b1 = *(const float4*)&B1s[kk][tx*4];
            float4 b3 = *(const float4*)&B3s[kk][tx*4];
            float aa[4]  = {a.x,a.y,a.z,a.w};
            float bb1[4] = {b1.x,b1.y,b1.z,b1.w};
            float bb3[4] = {b3.x,b3.y,b3.z,b3.w};
            #pragma unroll
            for (int i = 0; i < 4; ++i)
                #pragma unroll
                for (int j = 0; j < 4; ++j) {
                    c1[i][j] = fmaf(aa[i], bb1[j], c1[i][j]);
                    c3[i][j] = fmaf(aa[i], bb3[j], c3[i][j]);
                }
        }
    }

    #pragma unroll
    for (int i = 0; i < 4; ++i) {
        int ml = ty*4 + i;
        if (ml < rows) {
            int pos = base_pos + mtile*64 + ml;
            float* dst = g_act + (size_t)pos * II + n0 + tx*4;
            #pragma unroll
            for (int j = 0; j < 4; ++j) {
                float v1 = c1[i][j];
                float sig = 1.f / (1.f + expf(-v1));
                dst[j] = v1 * sig * c3[i][j];
            }
        }
    }
}

// ---------------- phase B: y = act W2^T per pair ----------------
// grid: (HH/64, EE+1, 32) ; block 256
__global__ __launch_bounds__(256) void phaseB_kernel(
        const float* __restrict__ w2,
        const float* __restrict__ ws2)
{
    const int g = blockIdx.y;
    int m_count, base_pos;
    const float* W2;
    if (g < EE) {
        m_count = g_counts[g]; base_pos = g_offsets[g];
        W2 = w2 + (size_t)g * HH * II;
    } else {
        m_count = TT; base_pos = NROUTED; W2 = ws2;
    }
    const int mtile = blockIdx.z;
    if (mtile * 64 >= m_count) return;
    const int rows = min(64, m_count - mtile * 64);
    const int n0 = blockIdx.x * 64;

    __shared__ float As[16][64];
    __shared__ float Bs[16][64];

    const int tid = threadIdx.x;
    const int tx = tid & 15, ty = tid >> 4;
    float c[4][4] = {{0}};

    const int lr = tid >> 2;
    const int lk = (tid & 3) * 4;
    const int apos = base_pos + mtile*64 + min(lr, rows - 1);
    const float* arow = g_act + (size_t)apos * II;
    const float* brow = W2 + (size_t)(n0 + lr) * II;

    for (int k0 = 0; k0 < II; k0 += 16) {
        float4 av = *(const float4*)(arow + k0 + lk);
        float4 bv = *(const float4*)(brow + k0 + lk);
        __syncthreads();
        As[lk+0][lr]=av.x; As[lk+1][lr]=av.y; As[lk+2][lr]=av.z; As[lk+3][lr]=av.w;
        Bs[lk+0][lr]=bv.x; Bs[lk+1][lr]=bv.y; Bs[lk+2][lr]=bv.z; Bs[lk+3][lr]=bv.w;
        __syncthreads();
        #pragma unroll
        for (int kk = 0; kk < 16; ++kk) {
            float4 a = *(const float4*)&As[kk][ty*4];
            float4 b = *(const float4*)&Bs[kk][tx*4];
            float aa[4] = {a.x,a.y,a.z,a.w};
            float bb[4] = {b.x,b.y,b.z,b.w};
            #pragma unroll
            for (int i = 0; i < 4; ++i)
                #pragma unroll
                for (int j = 0; j < 4; ++j)
                    c[i][j] = fmaf(aa[i], bb[j], c[i][j]);
        }
    }

    #pragma unroll
    for (int i = 0; i < 4; ++i) {
        int ml = ty*4 + i;
        if (ml < rows) {
            int pos = base_pos + mtile*64 + ml;
            float* dst = g_pairout + (size_t)pos * HH + n0 + tx*4;
            #pragma unroll
            for (int j = 0; j < 4; ++j) dst[j] = c[i][j];
        }
    }
}

// ---------------- combine: out[t] = shared[t] + sum_j w_j * pairout[pos_j] ----------------
__global__ __launch_bounds__(256) void combine_kernel(float* __restrict__ out)
{
    const int t = blockIdx.x;
    const int tid = threadIdx.x;
    __shared__ float w[TOPK];
    __shared__ int   pos[TOPK];
    if (tid < TOPK) {
        w[tid]   = g_topk_w[t*TOPK + tid];
        pos[tid] = g_pair_pos[t*TOPK + tid];
    }
    __syncthreads();
    const float4* sh = (const float4*)(g_pairout + (size_t)(NROUTED + t) * HH);
    const float4* p0 = (const float4*)(g_pairout + (size_t)pos[0] * HH);
    const float4* p1 = (const float4*)(g_pairout + (size_t)pos[1] * HH);
    const float4* p2 = (const float4*)(g_pairout + (size_t)pos[2] * HH);
    const float4* p3 = (const float4*)(g_pairout + (size_t)pos[3] * HH);
    float4* o = (float4*)(out + (size_t)t * HH);
    const float w0=w[0], w1=w[1], w2=w[2], w3=w[3];
    #pragma unroll
    for (int it = 0; it < HH/4/256; ++it) {
        int i = tid + it*256;
        float4 acc = sh[i];
        float4 v0 = p0[i], v1 = p1[i], v2 = p2[i], v3 = p3[i];
        acc.x += w0*v0.x + w1*v1.x + w2*v2.x + w3*v3.x;
        acc.y += w0*v0.y + w1*v1.y + w2*v2.y + w3*v3.y;
        acc.z += w0*v0.z + w1*v1.z + w2*v2.z + w3*v3.z;
        acc.w += w0*v0.w + w1*v1.w + w2*v2.w + w3*v3.w;
        o[i] = acc;
    }
}

// ---------------- launch ----------------
extern "C" void kernel_launch(void* const* d_in, const int* in_sizes, int n_in,
                              void* d_out, int out_size)
{
    const float* x    = (const float*)d_in[0];
    const float* gw   = (const float*)d_in[1];
    const float* bias = (const float*)d_in[2];
    const float* w1   = (const float*)d_in[3];
    const float* w3   = (const float*)d_in[4];
    const float* w2   = (const float*)d_in[5];
    const float* ws1  = (const float*)d_in[6];
    const float* ws3  = (const float*)d_in[7];
    const float* ws2  = (const float*)d_in[8];
    float* out = (float*)d_out;

    zero_kernel<<<1, 64>>>();
    gate_kernel<<<TT/4, 256>>>(x, gw, bias);
    offsets_kernel<<<1, 32>>>();
    scatter_kernel<<<TT/256, 256>>>();
    phaseA_kernel<<<dim3(II/64, EE+1, 32), 256>>>(x, w1, w3, ws1, ws3);
    phaseB_kernel<<<dim3(HH/64, EE+1, 32), 256>>>(w2, ws2);
    combine_kernel<<<TT, 256>>>(out);
}

// round 3
// speedup vs baseline: 1.6458x; 1.6458x over previous
#include <cuda_runtime.h>
#include <math.h>

#define TT 2048      // tokens
#define HH 2048      // hidden
#define II 1024      // moe intermediate
#define EE 32        // routed experts
#define TOPK 4
#define NROUTED (TT*TOPK)       // 8192
#define NPAIRS  (NROUTED + TT)  // 10240 (routed pairs + shared-expert rows)

// ---------------- device scratch (static: no allocation allowed) ----------------
__device__ int   g_counts[EE];
__device__ int   g_cursor[EE];
__device__ int   g_offsets[EE];
__device__ int   g_topk_idx[NROUTED];
__device__ float g_topk_w[NROUTED];
__device__ int   g_pair_token[NROUTED];   // pos -> token
__device__ int   g_pair_pos[NROUTED];     // t*4+j -> pos
__device__ float g_act[(size_t)NPAIRS * II];       // ~42 MB
__device__ float g_pairout[(size_t)NPAIRS * HH];   // ~84 MB

// ---------------- misc small kernels ----------------
__global__ void zero_kernel() {
    int i = threadIdx.x;
    if (i < EE) { g_counts[i] = 0; g_cursor[i] = 0; }
}

__global__ void offsets_kernel() {
    if (threadIdx.x == 0) {
        int s = 0;
        for (int e = 0; e < EE; ++e) { g_offsets[e] = s; s += g_counts[e]; }
    }
}

__global__ void scatter_kernel() {
    int t = blockIdx.x * blockDim.x + threadIdx.x;
    if (t >= TT) return;
    #pragma unroll
    for (int j = 0; j < TOPK; ++j) {
        int e = g_topk_idx[t*TOPK + j];
        int pos = g_offsets[e] + atomicAdd(&g_cursor[e], 1);
        g_pair_token[pos] = t;
        g_pair_pos[t*TOPK + j] = pos;
    }
}

// ---------------- gate + routing: 4 tokens per block ----------------
__global__ __launch_bounds__(256) void gate_kernel(
        const float* __restrict__ x,
        const float* __restrict__ gw,
        const float* __restrict__ bias)
{
    __shared__ float xs[4][HH];
    __shared__ float logits_s[4][EE];
    __shared__ float bias_s[EE];

    int tid = threadIdx.x;
    int t0  = blockIdx.x * 4;

    // load 4 token rows (4*2048 floats = 2048 float4)
    const float4* xg  = (const float4*)(x + (size_t)t0 * HH);
    float4*       xs4 = (float4*)&xs[0][0];
    #pragma unroll
    for (int i = 0; i < 8; ++i) xs4[tid + i*256] = xg[tid + i*256];
    if (tid < EE) bias_s[tid] = bias[tid];
    __syncthreads();

    int warp = tid >> 5, lane = tid & 31;

    // 8 warps x 4 experts each, 4 tokens per dot
    #pragma unroll
    for (int ei = 0; ei < 4; ++ei) {
        int e = warp*4 + ei;
        const float* gr = gw + (size_t)e * HH;
        float a0=0.f, a1=0.f, a2=0.f, a3=0.f;
        for (int h = lane; h < HH; h += 32) {
            float g = gr[h];
            a0 = fmaf(g, xs[0][h], a0);
            a1 = fmaf(g, xs[1][h], a1);
            a2 = fmaf(g, xs[2][h], a2);
            a3 = fmaf(g, xs[3][h], a3);
        }
        #pragma unroll
        for (int off = 16; off; off >>= 1) {
            a0 += __shfl_xor_sync(0xffffffffu, a0, off);
            a1 += __shfl_xor_sync(0xffffffffu, a1, off);
            a2 += __shfl_xor_sync(0xffffffffu, a2, off);
            a3 += __shfl_xor_sync(0xffffffffu, a3, off);
        }
        if (lane == 0) {
            logits_s[0][e] = a0; logits_s[1][e] = a1;
            logits_s[2][e] = a2; logits_s[3][e] = a3;
        }
    }
    __syncthreads();

    // warps 0..3: routing for token t0+warp, lane = expert
    if (warp < 4) {
        int t = t0 + warp;
        float logit = logits_s[warp][lane];
        float s   = 1.f / (1.f + expf(-logit));     // sigmoid score
        float sfc = s + bias_s[lane];               // biased score for choice

        // --- group score: sum of top-2 within each 8-lane group ---
        float m1 = sfc, m2 = -INFINITY;
        #pragma unroll
        for (int off = 4; off >= 1; off >>= 1) {    // xor 4,2,1 stays inside 8-lane group
            float o1 = __shfl_xor_sync(0xffffffffu, m1, off);
            float o2 = __shfl_xor_sync(0xffffffffu, m2, off);
            float hi = fmaxf(m1, o1);
            float lo = fmaxf(fminf(m1, o1), fmaxf(m2, o2));
            m1 = hi; m2 = lo;
        }
        float gs = m1 + m2;
        float gv[4];
        gv[0] = __shfl_sync(0xffffffffu, gs, 0);
        gv[1] = __shfl_sync(0xffffffffu, gs, 8);
        gv[2] = __shfl_sync(0xffffffffu, gs, 16);
        gv[3] = __shfl_sync(0xffffffffu, gs, 24);

        // top-2 groups (strict >, so ties keep lower index == lax.top_k)
        int b1 = 0; float v1 = gv[0];
        #pragma unroll
        for (int gg = 1; gg < 4; ++gg) if (gv[gg] > v1) { v1 = gv[gg]; b1 = gg; }
        int b2 = -1; float v2 = -INFINITY;
        #pragma unroll
        for (int gg = 0; gg < 4; ++gg) {
            if (gg == b1) continue;
            if (gv[gg] > v2) { v2 = gv[gg]; b2 = gg; }
        }

        int mygrp = lane >> 3;
        float val = (mygrp == b1 || mygrp == b2) ? sfc : 0.0f;  // match jnp.where(...,0.0)

        // --- top-4 experts on masked biased scores (lower-index tiebreak) ---
        int   sel_i[TOPK];
        float sel_w[TOPK];
        float cur = val;
        #pragma unroll
        for (int j = 0; j < TOPK; ++j) {
            float bv = cur; int bi = lane;
            #pragma unroll
            for (int off = 16; off >= 1; off >>= 1) {
                float ov = __shfl_xor_sync(0xffffffffu, bv, off);
                int   oi = __shfl_xor_sync(0xffffffffu, bi, off);
                if (ov > bv || (ov == bv && oi < bi)) { bv = ov; bi = oi; }
            }
            sel_i[j] = bi;
            sel_w[j] = __shfl_sync(0xffffffffu, s, bi);  // UNbiased sigmoid score
            if (lane == bi) cur = -INFINITY;
        }
        if (lane == 0) {
            float sum = sel_w[0] + sel_w[1] + sel_w[2] + sel_w[3];
            float scale = 2.5f / (sum + 1e-20f);
            #pragma unroll
            for (int j = 0; j < TOPK; ++j) {
                g_topk_idx[t*TOPK + j] = sel_i[j];
                g_topk_w[t*TOPK + j]   = sel_w[j] * scale;
                atomicAdd(&g_counts[sel_i[j]], 1);
            }
        }
    }
}

// ---------------- phase A: act = silu(X W1^T) * (X W3^T), expert-gathered ----------------
// grid: (II/64, EE+1, 32) ; block 256
__global__ __launch_bounds__(256) void phaseA_kernel(
        const float* __restrict__ x,
        const float* __restrict__ w1,
        const float* __restrict__ w3,
        const float* __restrict__ ws1,
        const float* __restrict__ ws3)
{
    const int g = blockIdx.y;
    int m_count, base_pos;
    const float *W1, *W3;
    if (g < EE) {
        m_count = g_counts[g]; base_pos = g_offsets[g];
        W1 = w1 + (size_t)g * II * HH; W3 = w3 + (size_t)g * II * HH;
    } else {
        m_count = TT; base_pos = NROUTED; W1 = ws1; W3 = ws3;
    }
    const int mtile = blockIdx.z;
    if (mtile * 64 >= m_count) return;
    const int rows = min(64, m_count - mtile * 64);
    const int n0 = blockIdx.x * 64;

    __shared__ float As [16][64];
    __shared__ float B1s[16][64];
    __shared__ float B3s[16][64];
    __shared__ int   toks[64];

    const int tid = threadIdx.x;
    if (tid < 64) {
        int r = min(tid, rows - 1);
        toks[tid] = (g < EE) ? g_pair_token[base_pos + mtile*64 + r] : (mtile*64 + tid);
    }
    __syncthreads();

    const int tx = tid & 15, ty = tid >> 4;
    float c1[4][4] = {{0}}, c3[4][4] = {{0}};

    const int lr = tid >> 2;          // 0..63
    const int lk = (tid & 3) * 4;     // 0,4,8,12
    const float* arow  = x  + (size_t)toks[lr] * HH;
    const float* b1row = W1 + (size_t)(n0 + lr) * HH;
    const float* b3row = W3 + (size_t)(n0 + lr) * HH;

    for (int k0 = 0; k0 < HH; k0 += 16) {
        float4 av  = *(const float4*)(arow  + k0 + lk);
        float4 b1v = *(const float4*)(b1row + k0 + lk);
        float4 b3v = *(const float4*)(b3row + k0 + lk);
        __syncthreads();
        As [lk+0][lr]=av.x;  As [lk+1][lr]=av.y;  As [lk+2][lr]=av.z;  As [lk+3][lr]=av.w;
        B1s[lk+0][lr]=b1v.x; B1s[lk+1][lr]=b1v.y; B1s[lk+2][lr]=b1v.z; B1s[lk+3][lr]=b1v.w;
        B3s[lk+0][lr]=b3v.x; B3s[lk+1][lr]=b3v.y; B3s[lk+2][lr]=b3v.z; B3s[lk+3][lr]=b3v.w;
        __syncthreads();
        #pragma unroll
        for (int kk = 0; kk < 16; ++kk) {
            float4 a  = *(const float4*)&As [kk][ty*4];
            float4 b1 = *(const float4*)&B1s[kk][tx*4];
            float4 b3 = *(const float4*)&B3s[kk][tx*4];
            float aa[4]  = {a.x,a.y,a.z,a.w};
            float bb1[4] = {b1.x,b1.y,b1.z,b1.w};
            float bb3[4] = {b3.x,b3.y,b3.z,b3.w};
            #pragma unroll
            for (int i = 0; i < 4; ++i)
                #pragma unroll
                for (int j = 0; j < 4; ++j) {
                    c1[i][j] = fmaf(aa[i], bb1[j], c1[i][j]);
                    c3[i][j] = fmaf(aa[i], bb3[j], c3[i][j]);
                }
        }
    }

    #pragma unroll
    for (int i = 0; i < 4; ++i) {
        int ml = ty*4 + i;
        if (ml < rows) {
            int pos = base_pos + mtile*64 + ml;
            float* dst = g_act + (size_t)pos * II + n0 + tx*4;
            #pragma unroll
            for (int j = 0; j < 4; ++j) {
                float v1 = c1[i][j];
                float sig = 1.f / (1.f + expf(-v1));
                dst[j] = v1 * sig * c3[i][j];
            }
        }
    }
}

// ---------------- phase B: y = act W2^T per pair ----------------
// grid: (HH/64, EE+1, 32) ; block 256
__global__ __launch_bounds__(256) void phaseB_kernel(
        const float* __restrict__ w2,
        const float* __restrict__ ws2)
{
    const int g = blockIdx.y;
    int m_count, base_pos;
    const float* W2;
    if (g < EE) {
        m_count = g_counts[g]; base_pos = g_offsets[g];
        W2 = w2 + (size_t)g * HH * II;
    } else {
        m_count = TT; base_pos = NROUTED; W2 = ws2;
    }
    const int mtile = blockIdx.z;
    if (mtile * 64 >= m_count) return;
    const int rows = min(64, m_count - mtile * 64);
    const int n0 = blockIdx.x * 64;

    __shared__ float As[16][64];
    __shared__ float Bs[16][64];

    const int tid = threadIdx.x;
    const int tx = tid & 15, ty = tid >> 4;
    float c[4][4] = {{0}};

    const int lr = tid >> 2;
    const int lk = (tid & 3) * 4;
    const int apos = base_pos + mtile*64 + min(lr, rows - 1);
    const float* arow = g_act + (size_t)apos * II;
    const float* brow = W2 + (size_t)(n0 + lr) * II;

    for (int k0 = 0; k0 < II; k0 += 16) {
        float4 av = *(const float4*)(arow + k0 + lk);
        float4 bv = *(const float4*)(brow + k0 + lk);
        __syncthreads();
        As[lk+0][lr]=av.x; As[lk+1][lr]=av.y; As[lk+2][lr]=av.z; As[lk+3][lr]=av.w;
        Bs[lk+0][lr]=bv.x; Bs[lk+1][lr]=bv.y; Bs[lk+2][lr]=bv.z; Bs[lk+3][lr]=bv.w;
        __syncthreads();
        #pragma unroll
        for (int kk = 0; kk < 16; ++kk) {
            float4 a = *(const float4*)&As[kk][ty*4];
            float4 b = *(const float4*)&Bs[kk][tx*4];
            float aa[4] = {a.x,a.y,a.z,a.w};
            float bb[4] = {b.x,b.y,b.z,b.w};
            #pragma unroll
            for (int i = 0; i < 4; ++i)
                #pragma unroll
                for (int j = 0; j < 4; ++j)
                    c[i][j] = fmaf(aa[i], bb[j], c[i][j]);
        }
    }

    #pragma unroll
    for (int i = 0; i < 4; ++i) {
        int ml = ty*4 + i;
        if (ml < rows) {
            int pos = base_pos + mtile*64 + ml;
            float* dst = g_pairout + (size_t)pos * HH + n0 + tx*4;
            #pragma unroll
            for (int j = 0; j < 4; ++j) dst[j] = c[i][j];
        }
    }
}

// ---------------- combine: out[t] = shared[t] + sum_j w_j * pairout[pos_j] ----------------
__global__ __launch_bounds__(256) void combine_kernel(float* __restrict__ out)
{
    const int t = blockIdx.x;
    const int tid = threadIdx.x;
    __shared__ float w[TOPK];
    __shared__ int   pos[TOPK];
    if (tid < TOPK) {
        w[tid]   = g_topk_w[t*TOPK + tid];
        pos[tid] = g_pair_pos[t*TOPK + tid];
    }
    __syncthreads();
    const float4* sh = (const float4*)(g_pairout + (size_t)(NROUTED + t) * HH);
    const float4* p0 = (const float4*)(g_pairout + (size_t)pos[0] * HH);
    const float4* p1 = (const float4*)(g_pairout + (size_t)pos[1] * HH);
    const float4* p2 = (const float4*)(g_pairout + (size_t)pos[2] * HH);
    const float4* p3 = (const float4*)(g_pairout + (size_t)pos[3] * HH);
    float4* o = (float4*)(out + (size_t)t * HH);
    const float w0=w[0], w1=w[1], w2=w[2], w3=w[3];
    #pragma unroll
    for (int it = 0; it < HH/4/256; ++it) {
        int i = tid + it*256;
        float4 acc = sh[i];
        float4 v0 = p0[i], v1 = p1[i], v2 = p2[i], v3 = p3[i];
        acc.x += w0*v0.x + w1*v1.x + w2*v2.x + w3*v3.x;
        acc.y += w0*v0.y + w1*v1.y + w2*v2.y + w3*v3.y;
        acc.z += w0*v0.z + w1*v1.z + w2*v2.z + w3*v3.z;
        acc.w += w0*v0.w + w1*v1.w + w2*v2.w + w3*v3.w;
        o[i] = acc;
    }
}

// ---------------- launch ----------------
extern "C" void kernel_launch(void* const* d_in, const int* in_sizes, int n_in,
                              void* d_out, int out_size)
{
    const float* x    = (const float*)d_in[0];
    const float* gw   = (const float*)d_in[1];
    const float* bias = (const float*)d_in[2];
    const float* w1   = (const float*)d_in[3];
    const float* w3   = (const float*)d_in[4];
    const float* w2   = (const float*)d_in[5];
    const float* ws1  = (const float*)d_in[6];
    const float* ws3  = (const float*)d_in[7];
    const float* ws2  = (const float*)d_in[8];
    float* out = (float*)d_out;

    zero_kernel<<<1, 64>>>();
    gate_kernel<<<TT/4, 256>>>(x, gw, bias);
    offsets_kernel<<<1, 32>>>();
    scatter_kernel<<<TT/256, 256>>>();
    phaseA_kernel<<<dim3(II/64, EE+1, 32), 256>>>(x, w1, w3, ws1, ws3);
    phaseB_kernel<<<dim3(HH/64, EE+1, 32), 256>>>(w2, ws2);
    combine_kernel<<<TT, 256>>>(out);
}

// round 5
// speedup vs baseline: 4.3057x; 2.6161x over previous
#include <cuda_runtime.h>
#include <cuda_bf16.h>
#include <math.h>
#include <stdint.h>

#define TT 2048
#define HH 2048
#define II 1024
#define EE 32
#define TOPK 4
#define NROUTED (TT*TOPK)
#define NPAIRS  (NROUTED + TT)

// GEMM tiling
#define BM 128
#define BN 128
#define BK 32
#define ROWB 80                    // bytes per smem row (32 bf16 = 64B, padded to 80)
#define OFF_AHI 0
#define OFF_ALO 10240
#define OFF_BHI 20480
#define OFF_BLO 30720
#define BUFSZ   40960
#define SMEM_DYN (2*BUFSZ)

// ---------------- device scratch ----------------
__device__ int   g_counts[EE];
__device__ int   g_cursor[EE];
__device__ int   g_offsets[EE];
__device__ int   g_topk_idx[NROUTED];
__device__ float g_topk_w[NROUTED];
__device__ int   g_pair_token[NROUTED];
__device__ int   g_pair_pos[NROUTED];
__device__ __nv_bfloat16 g_xhi[(size_t)TT*HH];
__device__ __nv_bfloat16 g_xlo[(size_t)TT*HH];
__device__ float g_C1[(size_t)NPAIRS*II];
__device__ float g_C3[(size_t)NPAIRS*II];
__device__ __nv_bfloat16 g_acthi[(size_t)NPAIRS*II];
__device__ __nv_bfloat16 g_actlo[(size_t)NPAIRS*II];
__device__ float g_pairout[(size_t)NPAIRS*HH];

// ---------------- helpers ----------------
__device__ __forceinline__ void cvt2bf(unsigned &r, float hi_elem, float lo_elem) {
    asm("cvt.rn.bf16x2.f32 %0, %1, %2;" : "=r"(r) : "f"(hi_elem), "f"(lo_elem));
}
__device__ __forceinline__ void ldsm4(unsigned &r0, unsigned &r1, unsigned &r2, unsigned &r3,
                                      unsigned addr) {
    asm volatile("ldmatrix.sync.aligned.m8n8.x4.shared.b16 {%0,%1,%2,%3}, [%4];"
                 : "=r"(r0), "=r"(r1), "=r"(r2), "=r"(r3) : "r"(addr));
}
__device__ __forceinline__ void mma16816(float* c, const unsigned* a, unsigned b0, unsigned b1) {
    asm volatile("mma.sync.aligned.m16n8k16.row.col.f32.bf16.bf16.f32 "
                 "{%0,%1,%2,%3}, {%4,%5,%6,%7}, {%8,%9}, {%0,%1,%2,%3};"
                 : "+f"(c[0]), "+f"(c[1]), "+f"(c[2]), "+f"(c[3])
                 : "r"(a[0]), "r"(a[1]), "r"(a[2]), "r"(a[3]), "r"(b0), "r"(b1));
}
__device__ __forceinline__ void cp16(unsigned dst, const void* src) {
    asm volatile("cp.async.cg.shared.global [%0], [%1], 16;" :: "r"(dst), "l"(src));
}

// ---------------- small kernels ----------------
__global__ void zero_kernel() {
    int i = threadIdx.x;
    if (i < EE) { g_counts[i] = 0; g_cursor[i] = 0; }
}
__global__ void offsets_kernel() {
    if (threadIdx.x == 0) {
        int s = 0;
        for (int e = 0; e < EE; ++e) { g_offsets[e] = s; s += g_counts[e]; }
    }
}
__global__ void scatter_kernel() {
    int t = blockIdx.x * blockDim.x + threadIdx.x;
    if (t >= TT) return;
    #pragma unroll
    for (int j = 0; j < TOPK; ++j) {
        int e = g_topk_idx[t*TOPK + j];
        int pos = g_offsets[e] + atomicAdd(&g_cursor[e], 1);
        g_pair_token[pos] = t;
        g_pair_pos[t*TOPK + j] = pos;
    }
}
__global__ __launch_bounds__(256) void convx_kernel(const float* __restrict__ x) {
    int i = blockIdx.x * 256 + threadIdx.x;
    float v = x[i];
    __nv_bfloat16 h = __float2bfloat16(v);
    g_xhi[i] = h;
    g_xlo[i] = __float2bfloat16(v - __bfloat162float(h));
}
// act = silu(C1)*C3 -> bf16 hi/lo planes
__global__ __launch_bounds__(256) void act_kernel() {
    size_t i4 = (size_t)blockIdx.x * 256 + threadIdx.x;
    float4 a = ((const float4*)g_C1)[i4];
    float4 b = ((const float4*)g_C3)[i4];
    float v[4];
    v[0] = a.x / (1.f + expf(-a.x)) * b.x;
    v[1] = a.y / (1.f + expf(-a.y)) * b.y;
    v[2] = a.z / (1.f + expf(-a.z)) * b.z;
    v[3] = a.w / (1.f + expf(-a.w)) * b.w;
    unsigned h01, h23, l01, l23;
    cvt2bf(h01, v[1], v[0]);
    cvt2bf(h23, v[3], v[2]);
    float r0 = v[0] - __uint_as_float(h01 << 16);
    float r1 = v[1] - __uint_as_float(h01 & 0xffff0000u);
    float r2 = v[2] - __uint_as_float(h23 << 16);
    float r3 = v[3] - __uint_as_float(h23 & 0xffff0000u);
    cvt2bf(l01, r1, r0);
    cvt2bf(l23, r3, r2);
    ((uint2*)g_acthi)[i4] = make_uint2(h01, h23);
    ((uint2*)g_actlo)[i4] = make_uint2(l01, l23);
}

// ---------------- gate + routing (proven in R1) ----------------
__global__ __launch_bounds__(256) void gate_kernel(
        const float* __restrict__ x, const float* __restrict__ gw,
        const float* __restrict__ bias)
{
    __shared__ float xs[4][HH];
    __shared__ float logits_s[4][EE];
    __shared__ float bias_s[EE];
    int tid = threadIdx.x;
    int t0  = blockIdx.x * 4;
    const float4* xg  = (const float4*)(x + (size_t)t0 * HH);
    float4*       xs4 = (float4*)&xs[0][0];
    #pragma unroll
    for (int i = 0; i < 8; ++i) xs4[tid + i*256] = xg[tid + i*256];
    if (tid < EE) bias_s[tid] = bias[tid];
    __syncthreads();
    int warp = tid >> 5, lane = tid & 31;
    #pragma unroll
    for (int ei = 0; ei < 4; ++ei) {
        int e = warp*4 + ei;
        const float* gr = gw + (size_t)e * HH;
        float a0=0.f, a1=0.f, a2=0.f, a3=0.f;
        for (int h = lane; h < HH; h += 32) {
            float g = gr[h];
            a0 = fmaf(g, xs[0][h], a0); a1 = fmaf(g, xs[1][h], a1);
            a2 = fmaf(g, xs[2][h], a2); a3 = fmaf(g, xs[3][h], a3);
        }
        #pragma unroll
        for (int off = 16; off; off >>= 1) {
            a0 += __shfl_xor_sync(0xffffffffu, a0, off);
            a1 += __shfl_xor_sync(0xffffffffu, a1, off);
            a2 += __shfl_xor_sync(0xffffffffu, a2, off);
            a3 += __shfl_xor_sync(0xffffffffu, a3, off);
        }
        if (lane == 0) {
            logits_s[0][e] = a0; logits_s[1][e] = a1;
            logits_s[2][e] = a2; logits_s[3][e] = a3;
        }
    }
    __syncthreads();
    if (warp < 4) {
        int t = t0 + warp;
        float logit = logits_s[warp][lane];
        float s   = 1.f / (1.f + expf(-logit));
        float sfc = s + bias_s[lane];
        float m1 = sfc, m2 = -INFINITY;
        #pragma unroll
        for (int off = 4; off >= 1; off >>= 1) {
            float o1 = __shfl_xor_sync(0xffffffffu, m1, off);
            float o2 = __shfl_xor_sync(0xffffffffu, m2, off);
            float hi = fmaxf(m1, o1);
            float lo = fmaxf(fminf(m1, o1), fmaxf(m2, o2));
            m1 = hi; m2 = lo;
        }
        float gs = m1 + m2;
        float gv[4];
        gv[0] = __shfl_sync(0xffffffffu, gs, 0);
        gv[1] = __shfl_sync(0xffffffffu, gs, 8);
        gv[2] = __shfl_sync(0xffffffffu, gs, 16);
        gv[3] = __shfl_sync(0xffffffffu, gs, 24);
        int b1 = 0; float v1 = gv[0];
        #pragma unroll
        for (int gg = 1; gg < 4; ++gg) if (gv[gg] > v1) { v1 = gv[gg]; b1 = gg; }
        int b2 = -1; float v2 = -INFINITY;
        #pragma unroll
        for (int gg = 0; gg < 4; ++gg) {
            if (gg == b1) continue;
            if (gv[gg] > v2) { v2 = gv[gg]; b2 = gg; }
        }
        int mygrp = lane >> 3;
        float val = (mygrp == b1 || mygrp == b2) ? sfc : 0.0f;
        int sel_i[TOPK]; float sel_w[TOPK];
        float cur = val;
        #pragma unroll
        for (int j = 0; j < TOPK; ++j) {
            float bv = cur; int bi = lane;
            #pragma unroll
            for (int off = 16; off >= 1; off >>= 1) {
                float ov = __shfl_xor_sync(0xffffffffu, bv, off);
                int   oi = __shfl_xor_sync(0xffffffffu, bi, off);
                if (ov > bv || (ov == bv && oi < bi)) { bv = ov; bi = oi; }
            }
            sel_i[j] = bi;
            sel_w[j] = __shfl_sync(0xffffffffu, s, bi);
            if (lane == bi) cur = -INFINITY;
        }
        if (lane == 0) {
            float sum = sel_w[0] + sel_w[1] + sel_w[2] + sel_w[3];
            float scale = 2.5f / (sum + 1e-20f);
            #pragma unroll
            for (int j = 0; j < TOPK; ++j) {
                g_topk_idx[t*TOPK + j] = sel_i[j];
                g_topk_w[t*TOPK + j]   = sel_w[j] * scale;
                atomicAdd(&g_counts[sel_i[j]], 1);
            }
        }
    }
}

// ---------------- grouped split-bf16 mma.sync GEMM ----------------
// C[group rows, N] = A @ W^T, A = hi+lo bf16 planes, W fp32 [N][K]
__global__ void __launch_bounds__(256) gemm_kernel(
    const __nv_bfloat16* __restrict__ Ahi, const __nv_bfloat16* __restrict__ Alo, int lda,
    const float* __restrict__ Wra, const float* __restrict__ Wsa,
    const float* __restrict__ Wrb, const float* __restrict__ Wsb,
    int Kdim, int ybnd, float* __restrict__ Ca, float* __restrict__ Cb,
    int ldc, int gather)
{
    const int g     = blockIdx.z;
    const int mtile = blockIdx.x;
    const int y     = blockIdx.y;

    int m_count, base_pos;
    if (g < EE) { m_count = g_counts[g]; base_pos = g_offsets[g]; }
    else        { m_count = TT;          base_pos = NROUTED; }
    if (mtile * BM >= m_count) return;
    const int rows = min(BM, m_count - mtile * BM);

    const size_t wsz = (size_t)II * HH;
    const float* W;
    float* C;
    int n0;
    if (y < ybnd) {
        W = (g < EE) ? (Wra + (size_t)g * wsz) : Wsa;
        C = Ca; n0 = y * BN;
    } else {
        W = (g < EE) ? (Wrb + (size_t)g * wsz) : Wsb;
        C = Cb; n0 = (y - ybnd) * BN;
    }

    extern __shared__ char sm[];
    __shared__ int s_toks[BM];
    const unsigned smb = (unsigned)__cvta_generic_to_shared(sm);

    const int tid = threadIdx.x;
    if (tid < BM) {
        int r = min(tid, rows - 1);
        int pos = base_pos + mtile*BM + r;
        s_toks[tid] = gather ? ((g < EE) ? g_pair_token[pos] : (mtile*BM + r)) : pos;
    }
    __syncthreads();

    const int S = Kdim / BK;
    const int warp = tid >> 5, lane = tid & 31;
    const int wm = (warp & 1) * 64;        // warp M offset
    const int wn = (warp >> 1) * 32;       // warp N offset
    const int l15 = lane & 15, lh = lane >> 4;

    float acc[4][4][4];
    #pragma unroll
    for (int i = 0; i < 4; ++i)
        #pragma unroll
        for (int j = 0; j < 4; ++j)
            #pragma unroll
            for (int q = 0; q < 4; ++q) acc[i][j][q] = 0.f;

    // ---- preload stage 0 ----
    {
        #pragma unroll
        for (int t = 0; t < 4; ++t) {
            int c = tid + t*256;
            int plane = c >> 9, cc = c & 511;
            int row = cc >> 2, ch = cc & 3;
            const __nv_bfloat16* src =
                (plane ? Alo : Ahi) + (size_t)s_toks[row]*lda + ch*8;
            cp16(smb + (plane ? OFF_ALO : OFF_AHI) + row*ROWB + ch*16, src);
        }
        asm volatile("cp.async.commit_group;");
        float4 bv[4];
        #pragma unroll
        for (int t = 0; t < 4; ++t) {
            int c = tid + t*256;
            int row = c >> 3, f4 = c & 7;
            bv[t] = *(const float4*)(W + (size_t)(n0+row)*Kdim + f4*4);
        }
        #pragma unroll
        for (int t = 0; t < 4; ++t) {
            int c = tid + t*256;
            int row = c >> 3, f4 = c & 7;
            unsigned h01, h23, l01, l23;
            cvt2bf(h01, bv[t].y, bv[t].x);
            cvt2bf(h23, bv[t].w, bv[t].z);
            float r0 = bv[t].x - __uint_as_float(h01 << 16);
            float r1 = bv[t].y - __uint_as_float(h01 & 0xffff0000u);
            float r2 = bv[t].z - __uint_as_float(h23 << 16);
            float r3 = bv[t].w - __uint_as_float(h23 & 0xffff0000u);
            cvt2bf(l01, r1, r0);
            cvt2bf(l23, r3, r2);
            *(uint2*)(sm + OFF_BHI + row*ROWB + f4*8) = make_uint2(h01, h23);
            *(uint2*)(sm + OFF_BLO + row*ROWB + f4*8) = make_uint2(l01, l23);
        }
        asm volatile("cp.async.wait_group 0;" ::: "memory");
        __syncthreads();
    }

    int buf = 0;
    for (int s = 0; s < S; ++s) {
        const unsigned cb = smb + buf * BUFSZ;
        const unsigned nb = smb + (buf ^ 1) * BUFSZ;
        char* nbg = sm + (buf ^ 1) * BUFSZ;
        float4 bv[4];
        const int k0n = (s + 1) * BK;
        if (s + 1 < S) {
            #pragma unroll
            for (int t = 0; t < 4; ++t) {
                int c = tid + t*256;
                int row = c >> 3, f4 = c & 7;
                bv[t] = *(const float4*)(W + (size_t)(n0+row)*Kdim + k0n + f4*4);
            }
            #pragma unroll
            for (int t = 0; t < 4; ++t) {
                int c = tid + t*256;
                int plane = c >> 9, cc = c & 511;
                int row = cc >> 2, ch = cc & 3;
                const __nv_bfloat16* src =
                    (plane ? Alo : Ahi) + (size_t)s_toks[row]*lda + k0n + ch*8;
                cp16(nb + (plane ? OFF_ALO : OFF_AHI) + row*ROWB + ch*16, src);
            }
            asm volatile("cp.async.commit_group;");
        }

        // ---- compute stage s ----
        #pragma unroll
        for (int kk = 0; kk < BK; kk += 16) {
            unsigned bh[2][4], bl[2][4];
            #pragma unroll
            for (int nf2 = 0; nf2 < 2; ++nf2) {
                unsigned addr = cb + OFF_BHI + (wn + nf2*16 + l15)*ROWB + (kk + lh*8)*2;
                ldsm4(bh[nf2][0], bh[nf2][1], bh[nf2][2], bh[nf2][3], addr);
                addr = cb + OFF_BLO + (wn + nf2*16 + l15)*ROWB + (kk + lh*8)*2;
                ldsm4(bl[nf2][0], bl[nf2][1], bl[nf2][2], bl[nf2][3], addr);
            }
            #pragma unroll
            for (int mf = 0; mf < 4; ++mf) {
                unsigned ah[4], al[4];
                unsigned addr = cb + OFF_AHI + (wm + mf*16 + l15)*ROWB + (kk + lh*8)*2;
                ldsm4(ah[0], ah[1], ah[2], ah[3], addr);
                addr = cb + OFF_ALO + (wm + mf*16 + l15)*ROWB + (kk + lh*8)*2;
                ldsm4(al[0], al[1], al[2], al[3], addr);
                #pragma unroll
                for (int nf2 = 0; nf2 < 2; ++nf2) {
                    #pragma unroll
                    for (int u = 0; u < 2; ++u) {
                        float* c = acc[mf][nf2*2 + u];
                        mma16816(c, ah, bh[nf2][u], bh[nf2][2 + u]);
                        mma16816(c, al, bh[nf2][u], bh[nf2][2 + u]);
                        mma16816(c, ah, bl[nf2][u], bl[nf2][2 + u]);
                    }
                }
            }
        }

        if (s + 1 < S) {
            #pragma unroll
            for (int t = 0; t < 4; ++t) {
                int c = tid + t*256;
                int row = c >> 3, f4 = c & 7;
                unsigned h01, h23, l01, l23;
                cvt2bf(h01, bv[t].y, bv[t].x);
                cvt2bf(h23, bv[t].w, bv[t].z);
                float r0 = bv[t].x - __uint_as_float(h01 << 16);
                float r1 = bv[t].y - __uint_as_float(h01 & 0xffff0000u);
                float r2 = bv[t].z - __uint_as_float(h23 << 16);
                float r3 = bv[t].w - __uint_as_float(h23 & 0xffff0000u);
                cvt2bf(l01, r1, r0);
                cvt2bf(l23, r3, r2);
                *(uint2*)(nbg + OFF_BHI + row*ROWB + f4*8) = make_uint2(h01, h23);
                *(uint2*)(nbg + OFF_BLO + row*ROWB + f4*8) = make_uint2(l01, l23);
            }
            asm volatile("cp.async.wait_group 0;" ::: "memory");
        }
        __syncthreads();
        buf ^= 1;
    }

    // ---- epilogue ----
    const int gq = lane >> 2, tau = lane & 3;
    #pragma unroll
    for (int mf = 0; mf < 4; ++mf) {
        #pragma unroll
        for (int nf = 0; nf < 4; ++nf) {
            int col = n0 + wn + nf*8 + tau*2;
            int r0 = wm + mf*16 + gq;
            int r1 = r0 + 8;
            if (r0 < rows) {
                float* d = C + (size_t)(base_pos + mtile*BM + r0) * ldc + col;
                d[0] = acc[mf][nf][0]; d[1] = acc[mf][nf][1];
            }
            if (r1 < rows) {
                float* d = C + (size_t)(base_pos + mtile*BM + r1) * ldc + col;
                d[0] = acc[mf][nf][2]; d[1] = acc[mf][nf][3];
            }
        }
    }
}

// ---------------- combine ----------------
__global__ __launch_bounds__(256) void combine_kernel(float* __restrict__ out)
{
    const int t = blockIdx.x;
    const int tid = threadIdx.x;
    __shared__ float w[TOPK];
    __shared__ int   pos[TOPK];
    if (tid < TOPK) {
        w[tid]   = g_topk_w[t*TOPK + tid];
        pos[tid] = g_pair_pos[t*TOPK + tid];
    }
    __syncthreads();
    const float4* sh = (const float4*)(g_pairout + (size_t)(NROUTED + t) * HH);
    const float4* p0 = (const float4*)(g_pairout + (size_t)pos[0] * HH);
    const float4* p1 = (const float4*)(g_pairout + (size_t)pos[1] * HH);
    const float4* p2 = (const float4*)(g_pairout + (size_t)pos[2] * HH);
    const float4* p3 = (const float4*)(g_pairout + (size_t)pos[3] * HH);
    float4* o = (float4*)(out + (size_t)t * HH);
    const float w0=w[0], w1=w[1], w2=w[2], w3=w[3];
    #pragma unroll
    for (int it = 0; it < HH/4/256; ++it) {
        int i = tid + it*256;
        float4 acc = sh[i];
        float4 v0 = p0[i], v1 = p1[i], v2 = p2[i], v3 = p3[i];
        acc.x += w0*v0.x + w1*v1.x + w2*v2.x + w3*v3.x;
        acc.y += w0*v0.y + w1*v1.y + w2*v2.y + w3*v3.y;
        acc.z += w0*v0.z + w1*v1.z + w2*v2.z + w3*v3.z;
        acc.w += w0*v0.w + w1*v1.w + w2*v2.w + w3*v3.w;
        o[i] = acc;
    }
}

// ---------------- launch ----------------
extern "C" void kernel_launch(void* const* d_in, const int* in_sizes, int n_in,
                              void* d_out, int out_size)
{
    const float* x    = (const float*)d_in[0];
    const float* gw   = (const float*)d_in[1];
    const float* bias = (const float*)d_in[2];
    const float* w1   = (const float*)d_in[3];
    const float* w3   = (const float*)d_in[4];
    const float* w2   = (const float*)d_in[5];
    const float* ws1  = (const float*)d_in[6];
    const float* ws3  = (const float*)d_in[7];
    const float* ws2  = (const float*)d_in[8];
    float* out = (float*)d_out;

    cudaFuncSetAttribute(gemm_kernel, cudaFuncAttributeMaxDynamicSharedMemorySize, SMEM_DYN);

    zero_kernel<<<1, 64>>>();
    gate_kernel<<<TT/4, 256>>>(x, gw, bias);
    offsets_kernel<<<1, 32>>>();
    scatter_kernel<<<TT/256, 256>>>();
    convx_kernel<<<TT*HH/256, 256>>>(x);

    __nv_bfloat16 *xhi, *xlo, *ahi, *alo;
    cudaGetSymbolAddress((void**)&xhi, g_xhi);
    cudaGetSymbolAddress((void**)&xlo, g_xlo);
    cudaGetSymbolAddress((void**)&ahi, g_acthi);
    cudaGetSymbolAddress((void**)&alo, g_actlo);
    float *c1, *c3, *po;
    cudaGetSymbolAddress((void**)&c1, g_C1);
    cudaGetSymbolAddress((void**)&c3, g_C3);
    cudaGetSymbolAddress((void**)&po, g_pairout);

    // phase A: C1 = X@W1^T (y<8), C3 = X@W3^T (y>=8); K=HH
    gemm_kernel<<<dim3(16, 16, EE+1), 256, SMEM_DYN>>>(
        xhi, xlo, HH, w1, ws1, w3, ws3, HH, 8, c1, c3, II, 1);
    act_kernel<<<(int)((size_t)NPAIRS*II/4/256), 256>>>();
    // phase B: pairout = act@W2^T; K=II
    gemm_kernel<<<dim3(16, 16, EE+1), 256, SMEM_DYN>>>(
        ahi, alo, II, w2, ws2, w2, ws2, II, 16, po, po, HH, 0);
    combine_kernel<<<TT, 256>>>(out);
}

// round 6
// speedup vs baseline: 6.0654x; 1.4087x over previous
#include <cuda_runtime.h>
#include <cuda_fp16.h>
#include <math.h>
#include <stdint.h>

#define TT 2048
#define HH 2048
#define II 1024
#define EE 32
#define TOPK 4
#define NROUTED (TT*TOPK)
#define NPAIRS  (NROUTED + TT)

// GEMM tiling
#define BM 128
#define BN 128
#define BK 32
#define ROWB 80                    // bytes per smem row (32 fp16 = 64B, padded to 80)
#define OFF_AHI 0
#define OFF_ALO 10240
#define OFF_BHI 20480
#define BUFSZ   30720
#define SMEM_DYN (2*BUFSZ)

// ---------------- device scratch ----------------
__device__ int   g_counts[EE];
__device__ int   g_cursor[EE];
__device__ int   g_offsets[EE];
__device__ int   g_topk_idx[NROUTED];
__device__ float g_topk_w[NROUTED];
__device__ int   g_pair_token[NROUTED];
__device__ int   g_pair_pos[NROUTED];
__device__ __half g_xhi[(size_t)TT*HH];
__device__ __half g_xlo[(size_t)TT*HH];
__device__ float g_C1[(size_t)NPAIRS*II];
__device__ float g_C3[(size_t)NPAIRS*II];
__device__ __half g_acthi[(size_t)NPAIRS*II];
__device__ __half g_actlo[(size_t)NPAIRS*II];
__device__ float g_pairout[(size_t)NPAIRS*HH];

// ---------------- helpers ----------------
__device__ __forceinline__ void cvt2h(unsigned &r, float hi_elem, float lo_elem) {
    // packs: upper16 = f16(hi_elem), lower16 = f16(lo_elem)
    asm("cvt.rn.f16x2.f32 %0, %1, %2;" : "=r"(r) : "f"(hi_elem), "f"(lo_elem));
}
__device__ __forceinline__ void ldsm4(unsigned &r0, unsigned &r1, unsigned &r2, unsigned &r3,
                                      unsigned addr) {
    asm volatile("ldmatrix.sync.aligned.m8n8.x4.shared.b16 {%0,%1,%2,%3}, [%4];"
                 : "=r"(r0), "=r"(r1), "=r"(r2), "=r"(r3) : "r"(addr));
}
__device__ __forceinline__ void mma16816(float* c, const unsigned* a, unsigned b0, unsigned b1) {
    asm volatile("mma.sync.aligned.m16n8k16.row.col.f32.f16.f16.f32 "
                 "{%0,%1,%2,%3}, {%4,%5,%6,%7}, {%8,%9}, {%0,%1,%2,%3};"
                 : "+f"(c[0]), "+f"(c[1]), "+f"(c[2]), "+f"(c[3])
                 : "r"(a[0]), "r"(a[1]), "r"(a[2]), "r"(a[3]), "r"(b0), "r"(b1));
}
__device__ __forceinline__ void cp16(unsigned dst, const void* src) {
    asm volatile("cp.async.cg.shared.global [%0], [%1], 16;" :: "r"(dst), "l"(src));
}

// ---------------- small kernels ----------------
__global__ void zero_kernel() {
    int i = threadIdx.x;
    if (i < EE) { g_counts[i] = 0; g_cursor[i] = 0; }
}
__global__ void offsets_kernel() {
    if (threadIdx.x == 0) {
        int s = 0;
        for (int e = 0; e < EE; ++e) { g_offsets[e] = s; s += g_counts[e]; }
    }
}
__global__ void scatter_kernel() {
    int t = blockIdx.x * blockDim.x + threadIdx.x;
    if (t >= TT) return;
    #pragma unroll
    for (int j = 0; j < TOPK; ++j) {
        int e = g_topk_idx[t*TOPK + j];
        int pos = g_offsets[e] + atomicAdd(&g_cursor[e], 1);
        g_pair_token[pos] = t;
        g_pair_pos[t*TOPK + j] = pos;
    }
}
__global__ __launch_bounds__(256) void convx_kernel(const float* __restrict__ x) {
    int i = blockIdx.x * 256 + threadIdx.x;
    float v = x[i];
    __half h = __float2half_rn(v);
    g_xhi[i] = h;
    g_xlo[i] = __float2half_rn(v - __half2float(h));
}
// act = silu(C1)*C3 -> fp16 hi/lo planes
__global__ __launch_bounds__(256) void act_kernel() {
    size_t i4 = (size_t)blockIdx.x * 256 + threadIdx.x;
    float4 a = ((const float4*)g_C1)[i4];
    float4 b = ((const float4*)g_C3)[i4];
    float v[4];
    v[0] = a.x / (1.f + expf(-a.x)) * b.x;
    v[1] = a.y / (1.f + expf(-a.y)) * b.y;
    v[2] = a.z / (1.f + expf(-a.z)) * b.z;
    v[3] = a.w / (1.f + expf(-a.w)) * b.w;
    unsigned h01, h23, l01, l23;
    cvt2h(h01, v[1], v[0]);
    cvt2h(h23, v[3], v[2]);
    float r0 = v[0] - __half2float(__ushort_as_half((unsigned short)(h01 & 0xffff)));
    float r1 = v[1] - __half2float(__ushort_as_half((unsigned short)(h01 >> 16)));
    float r2 = v[2] - __half2float(__ushort_as_half((unsigned short)(h23 & 0xffff)));
    float r3 = v[3] - __half2float(__ushort_as_half((unsigned short)(h23 >> 16)));
    cvt2h(l01, r1, r0);
    cvt2h(l23, r3, r2);
    ((uint2*)g_acthi)[i4] = make_uint2(h01, h23);
    ((uint2*)g_actlo)[i4] = make_uint2(l01, l23);
}

// ---------------- gate + routing (proven) ----------------
__global__ __launch_bounds__(256) void gate_kernel(
        const float* __restrict__ x, const float* __restrict__ gw,
        const float* __restrict__ bias)
{
    __shared__ float xs[4][HH];
    __shared__ float logits_s[4][EE];
    __shared__ float bias_s[EE];
    int tid = threadIdx.x;
    int t0  = blockIdx.x * 4;
    const float4* xg  = (const float4*)(x + (size_t)t0 * HH);
    float4*       xs4 = (float4*)&xs[0][0];
    #pragma unroll
    for (int i = 0; i < 8; ++i) xs4[tid + i*256] = xg[tid + i*256];
    if (tid < EE) bias_s[tid] = bias[tid];
    __syncthreads();
    int warp = tid >> 5, lane = tid & 31;
    #pragma unroll
    for (int ei = 0; ei < 4; ++ei) {
        int e = warp*4 + ei;
        const float* gr = gw + (size_t)e * HH;
        float a0=0.f, a1=0.f, a2=0.f, a3=0.f;
        for (int h = lane; h < HH; h += 32) {
            float g = gr[h];
            a0 = fmaf(g, xs[0][h], a0); a1 = fmaf(g, xs[1][h], a1);
            a2 = fmaf(g, xs[2][h], a2); a3 = fmaf(g, xs[3][h], a3);
        }
        #pragma unroll
        for (int off = 16; off; off >>= 1) {
            a0 += __shfl_xor_sync(0xffffffffu, a0, off);
            a1 += __shfl_xor_sync(0xffffffffu, a1, off);
            a2 += __shfl_xor_sync(0xffffffffu, a2, off);
            a3 += __shfl_xor_sync(0xffffffffu, a3, off);
        }
        if (lane == 0) {
            logits_s[0][e] = a0; logits_s[1][e] = a1;
            logits_s[2][e] = a2; logits_s[3][e] = a3;
        }
    }
    __syncthreads();
    if (warp < 4) {
        int t = t0 + warp;
        float logit = logits_s[warp][lane];
        float s   = 1.f / (1.f + expf(-logit));
        float sfc = s + bias_s[lane];
        float m1 = sfc, m2 = -INFINITY;
        #pragma unroll
        for (int off = 4; off >= 1; off >>= 1) {
            float o1 = __shfl_xor_sync(0xffffffffu, m1, off);
            float o2 = __shfl_xor_sync(0xffffffffu, m2, off);
            float hi = fmaxf(m1, o1);
            float lo = fmaxf(fminf(m1, o1), fmaxf(m2, o2));
            m1 = hi; m2 = lo;
        }
        float gs = m1 + m2;
        float gv[4];
        gv[0] = __shfl_sync(0xffffffffu, gs, 0);
        gv[1] = __shfl_sync(0xffffffffu, gs, 8);
        gv[2] = __shfl_sync(0xffffffffu, gs, 16);
        gv[3] = __shfl_sync(0xffffffffu, gs, 24);
        int b1 = 0; float v1 = gv[0];
        #pragma unroll
        for (int gg = 1; gg < 4; ++gg) if (gv[gg] > v1) { v1 = gv[gg]; b1 = gg; }
        int b2 = -1; float v2 = -INFINITY;
        #pragma unroll
        for (int gg = 0; gg < 4; ++gg) {
            if (gg == b1) continue;
            if (gv[gg] > v2) { v2 = gv[gg]; b2 = gg; }
        }
        int mygrp = lane >> 3;
        float val = (mygrp == b1 || mygrp == b2) ? sfc : 0.0f;
        int sel_i[TOPK]; float sel_w[TOPK];
        float cur = val;
        #pragma unroll
        for (int j = 0; j < TOPK; ++j) {
            float bv = cur; int bi = lane;
            #pragma unroll
            for (int off = 16; off >= 1; off >>= 1) {
                float ov = __shfl_xor_sync(0xffffffffu, bv, off);
                int   oi = __shfl_xor_sync(0xffffffffu, bi, off);
                if (ov > bv || (ov == bv && oi < bi)) { bv = ov; bi = oi; }
            }
            sel_i[j] = bi;
            sel_w[j] = __shfl_sync(0xffffffffu, s, bi);
            if (lane == bi) cur = -INFINITY;
        }
        if (lane == 0) {
            float sum = sel_w[0] + sel_w[1] + sel_w[2] + sel_w[3];
            float scale = 2.5f / (sum + 1e-20f);
            #pragma unroll
            for (int j = 0; j < TOPK; ++j) {
                g_topk_idx[t*TOPK + j] = sel_i[j];
                g_topk_w[t*TOPK + j]   = sel_w[j] * scale;
                atomicAdd(&g_counts[sel_i[j]], 1);
            }
        }
    }
}

// ---------------- grouped 2-term fp16 mma.sync GEMM ----------------
// C = A @ W_hi^T, A = (hi+lo) fp16 planes (exact A), W fp32 -> fp16 hi in-loader
__global__ void __launch_bounds__(256, 2) gemm_kernel(
    const __half* __restrict__ Ahi, const __half* __restrict__ Alo, int lda,
    const float* __restrict__ Wra, const float* __restrict__ Wsa,
    const float* __restrict__ Wrb, const float* __restrict__ Wsb,
    int Kdim, int ybnd, float* __restrict__ Ca, float* __restrict__ Cb,
    int ldc, int gather)
{
    const int g     = blockIdx.z;
    const int mtile = blockIdx.x;
    const int y     = blockIdx.y;

    int m_count, base_pos;
    if (g < EE) { m_count = g_counts[g]; base_pos = g_offsets[g]; }
    else        { m_count = TT;          base_pos = NROUTED; }
    if (mtile * BM >= m_count) return;
    const int rows = min(BM, m_count - mtile * BM);

    const size_t wsz = (size_t)II * HH;
    const float* W;
    float* C;
    int n0;
    if (y < ybnd) {
        W = (g < EE) ? (Wra + (size_t)g * wsz) : Wsa;
        C = Ca; n0 = y * BN;
    } else {
        W = (g < EE) ? (Wrb + (size_t)g * wsz) : Wsb;
        C = Cb; n0 = (y - ybnd) * BN;
    }

    extern __shared__ char sm[];
    __shared__ int s_toks[BM];
    const unsigned smb = (unsigned)__cvta_generic_to_shared(sm);

    const int tid = threadIdx.x;
    if (tid < BM) {
        int r = min(tid, rows - 1);
        int pos = base_pos + mtile*BM + r;
        s_toks[tid] = gather ? ((g < EE) ? g_pair_token[pos] : (mtile*BM + r)) : pos;
    }
    __syncthreads();

    const int S = Kdim / BK;
    const int warp = tid >> 5, lane = tid & 31;
    const int wm = (warp & 1) * 64;
    const int wn = (warp >> 1) * 32;
    const int l15 = lane & 15, lh = lane >> 4;

    float acc[4][4][4];
    #pragma unroll
    for (int i = 0; i < 4; ++i)
        #pragma unroll
        for (int j = 0; j < 4; ++j)
            #pragma unroll
            for (int q = 0; q < 4; ++q) acc[i][j][q] = 0.f;

    // ---- preload stage 0 ----
    {
        #pragma unroll
        for (int t = 0; t < 4; ++t) {
            int c = tid + t*256;
            int plane = c >> 9, cc = c & 511;
            int row = cc >> 2, ch = cc & 3;
            const __half* src = (plane ? Alo : Ahi) + (size_t)s_toks[row]*lda + ch*8;
            cp16(smb + (plane ? OFF_ALO : OFF_AHI) + row*ROWB + ch*16, src);
        }
        asm volatile("cp.async.commit_group;");
        float4 bv[4];
        #pragma unroll
        for (int t = 0; t < 4; ++t) {
            int c = tid + t*256;
            int row = c >> 3, f4 = c & 7;
            bv[t] = *(const float4*)(W + (size_t)(n0+row)*Kdim + f4*4);
        }
        #pragma unroll
        for (int t = 0; t < 4; ++t) {
            int c = tid + t*256;
            int row = c >> 3, f4 = c & 7;
            unsigned h01, h23;
            cvt2h(h01, bv[t].y, bv[t].x);
            cvt2h(h23, bv[t].w, bv[t].z);
            *(uint2*)(sm + OFF_BHI + row*ROWB + f4*8) = make_uint2(h01, h23);
        }
        asm volatile("cp.async.wait_group 0;" ::: "memory");
        __syncthreads();
    }

    int buf = 0;
    for (int s = 0; s < S; ++s) {
        const unsigned cb = smb + buf * BUFSZ;
        const unsigned nb = smb + (buf ^ 1) * BUFSZ;
        char* nbg = sm + (buf ^ 1) * BUFSZ;
        float4 bv[4];
        const int k0n = (s + 1) * BK;
        if (s + 1 < S) {
            #pragma unroll
            for (int t = 0; t < 4; ++t) {
                int c = tid + t*256;
                int row = c >> 3, f4 = c & 7;
                bv[t] = *(const float4*)(W + (size_t)(n0+row)*Kdim + k0n + f4*4);
            }
            #pragma unroll
            for (int t = 0; t < 4; ++t) {
                int c = tid + t*256;
                int plane = c >> 9, cc = c & 511;
                int row = cc >> 2, ch = cc & 3;
                const __half* src = (plane ? Alo : Ahi) + (size_t)s_toks[row]*lda + k0n + ch*8;
                cp16(nb + (plane ? OFF_ALO : OFF_AHI) + row*ROWB + ch*16, src);
            }
            asm volatile("cp.async.commit_group;");
        }

        // ---- compute stage s: 2 terms ----
        #pragma unroll
        for (int kk = 0; kk < BK; kk += 16) {
            unsigned bh[2][4];
            #pragma unroll
            for (int nf2 = 0; nf2 < 2; ++nf2) {
                unsigned addr = cb + OFF_BHI + (wn + nf2*16 + l15)*ROWB + (kk + lh*8)*2;
                ldsm4(bh[nf2][0], bh[nf2][1], bh[nf2][2], bh[nf2][3], addr);
            }
            #pragma unroll
            for (int mf = 0; mf < 4; ++mf) {
                unsigned ah[4], al[4];
                unsigned addr = cb + OFF_AHI + (wm + mf*16 + l15)*ROWB + (kk + lh*8)*2;
                ldsm4(ah[0], ah[1], ah[2], ah[3], addr);
                addr = cb + OFF_ALO + (wm + mf*16 + l15)*ROWB + (kk + lh*8)*2;
                ldsm4(al[0], al[1], al[2], al[3], addr);
                #pragma unroll
                for (int nf2 = 0; nf2 < 2; ++nf2) {
                    #pragma unroll
                    for (int u = 0; u < 2; ++u) {
                        float* c = acc[mf][nf2*2 + u];
                        mma16816(c, ah, bh[nf2][u], bh[nf2][2 + u]);
                        mma16816(c, al, bh[nf2][u], bh[nf2][2 + u]);
                    }
                }
            }
        }

        if (s + 1 < S) {
            #pragma unroll
            for (int t = 0; t < 4; ++t) {
                int c = tid + t*256;
                int row = c >> 3, f4 = c & 7;
                unsigned h01, h23;
                cvt2h(h01, bv[t].y, bv[t].x);
                cvt2h(h23, bv[t].w, bv[t].z);
                *(uint2*)(nbg + OFF_BHI + row*ROWB + f4*8) = make_uint2(h01, h23);
            }
            asm volatile("cp.async.wait_group 0;" ::: "memory");
        }
        __syncthreads();
        buf ^= 1;
    }

    // ---- epilogue ----
    const int gq = lane >> 2, tau = lane & 3;
    #pragma unroll
    for (int mf = 0; mf < 4; ++mf) {
        #pragma unroll
        for (int nf = 0; nf < 4; ++nf) {
            int col = n0 + wn + nf*8 + tau*2;
            int r0 = wm + mf*16 + gq;
            int r1 = r0 + 8;
            if (r0 < rows) {
                float* d = C + (size_t)(base_pos + mtile*BM + r0) * ldc + col;
                d[0] = acc[mf][nf][0]; d[1] = acc[mf][nf][1];
            }
            if (r1 < rows) {
                float* d = C + (size_t)(base_pos + mtile*BM + r1) * ldc + col;
                d[0] = acc[mf][nf][2]; d[1] = acc[mf][nf][3];
            }
        }
    }
}

// ---------------- combine ----------------
__global__ __launch_bounds__(256) void combine_kernel(float* __restrict__ out)
{
    const int t = blockIdx.x;
    const int tid = threadIdx.x;
    __shared__ float w[TOPK];
    __shared__ int   pos[TOPK];
    if (tid < TOPK) {
        w[tid]   = g_topk_w[t*TOPK + tid];
        pos[tid] = g_pair_pos[t*TOPK + tid];
    }
    __syncthreads();
    const float4* sh = (const float4*)(g_pairout + (size_t)(NROUTED + t) * HH);
    const float4* p0 = (const float4*)(g_pairout + (size_t)pos[0] * HH);
    const float4* p1 = (const float4*)(g_pairout + (size_t)pos[1] * HH);
    const float4* p2 = (const float4*)(g_pairout + (size_t)pos[2] * HH);
    const float4* p3 = (const float4*)(g_pairout + (size_t)pos[3] * HH);
    float4* o = (float4*)(out + (size_t)t * HH);
    const float w0=w[0], w1=w[1], w2=w[2], w3=w[3];
    #pragma unroll
    for (int it = 0; it < HH/4/256; ++it) {
        int i = tid + it*256;
        float4 acc = sh[i];
        float4 v0 = p0[i], v1 = p1[i], v2 = p2[i], v3 = p3[i];
        acc.x += w0*v0.x + w1*v1.x + w2*v2.x + w3*v3.x;
        acc.y += w0*v0.y + w1*v1.y + w2*v2.y + w3*v3.y;
        acc.z += w0*v0.z + w1*v1.z + w2*v2.z + w3*v3.z;
        acc.w += w0*v0.w + w1*v1.w + w2*v2.w + w3*v3.w;
        o[i] = acc;
    }
}

// ---------------- launch ----------------
extern "C" void kernel_launch(void* const* d_in, const int* in_sizes, int n_in,
                              void* d_out, int out_size)
{
    const float* x    = (const float*)d_in[0];
    const float* gw   = (const float*)d_in[1];
    const float* bias = (const float*)d_in[2];
    const float* w1   = (const float*)d_in[3];
    const float* w3   = (const float*)d_in[4];
    const float* w2   = (const float*)d_in[5];
    const float* ws1  = (const float*)d_in[6];
    const float* ws3  = (const float*)d_in[7];
    const float* ws2  = (const float*)d_in[8];
    float* out = (float*)d_out;

    cudaFuncSetAttribute(gemm_kernel, cudaFuncAttributeMaxDynamicSharedMemorySize, SMEM_DYN);

    zero_kernel<<<1, 64>>>();
    gate_kernel<<<TT/4, 256>>>(x, gw, bias);
    offsets_kernel<<<1, 32>>>();
    scatter_kernel<<<TT/256, 256>>>();
    convx_kernel<<<TT*HH/256, 256>>>(x);

    __half *xhi, *xlo, *ahi, *alo;
    cudaGetSymbolAddress((void**)&xhi, g_xhi);
    cudaGetSymbolAddress((void**)&xlo, g_xlo);
    cudaGetSymbolAddress((void**)&ahi, g_acthi);
    cudaGetSymbolAddress((void**)&alo, g_actlo);
    float *c1, *c3, *po;
    cudaGetSymbolAddress((void**)&c1, g_C1);
    cudaGetSymbolAddress((void**)&c3, g_C3);
    cudaGetSymbolAddress((void**)&po, g_pairout);

    // phase A: C1 = X@W1_hi^T (y<8), C3 = X@W3_hi^T (y>=8); K=HH
    gemm_kernel<<<dim3(16, 16, EE+1), 256, SMEM_DYN>>>(
        xhi, xlo, HH, w1, ws1, w3, ws3, HH, 8, c1, c3, II, 1);
    act_kernel<<<(int)((size_t)NPAIRS*II/4/256), 256>>>();
    // phase B: pairout = act@W2_hi^T; K=II
    gemm_kernel<<<dim3(16, 16, EE+1), 256, SMEM_DYN>>>(
        ahi, alo, II, w2, ws2, w2, ws2, II, 16, po, po, HH, 0);
    combine_kernel<<<TT, 256>>>(out);
}

// round 7
// speedup vs baseline: 8.6264x; 1.4222x over previous
#include <cuda_runtime.h>
#include <cuda_fp16.h>
#include <math.h>
#include <stdint.h>

#define TT 2048
#define HH 2048
#define II 1024
#define EE 32
#define TOPK 4
#define NROUTED (TT*TOPK)
#define NPAIRS  (NROUTED + TT)

// GEMM tiling
#define BM 128
#define BN 128
#define BK 32
#define ROWB 80                    // bytes per smem row (32 fp16 = 64B, padded to 80)
#define OFF_A 0
#define OFF_B 10240
#define BUFSZ 20480
#define SMEM_DYN (2*BUFSZ)

// ---------------- device scratch ----------------
__device__ int   g_counts[EE];
__device__ int   g_cursor[EE];
__device__ int   g_offsets[EE];
__device__ int   g_topk_idx[NROUTED];
__device__ float g_topk_w[NROUTED];
__device__ int   g_pair_token[NROUTED];
__device__ int   g_pair_pos[NROUTED];
__device__ __half g_xh[(size_t)TT*HH];
__device__ float g_C1[(size_t)NPAIRS*II];
__device__ float g_C3[(size_t)NPAIRS*II];
__device__ __half g_acth[(size_t)NPAIRS*II];
__device__ float g_pairout[(size_t)NPAIRS*HH];

// ---------------- helpers ----------------
__device__ __forceinline__ void cvt2h(unsigned &r, float hi_elem, float lo_elem) {
    asm("cvt.rn.f16x2.f32 %0, %1, %2;" : "=r"(r) : "f"(hi_elem), "f"(lo_elem));
}
__device__ __forceinline__ void ldsm4(unsigned &r0, unsigned &r1, unsigned &r2, unsigned &r3,
                                      unsigned addr) {
    asm volatile("ldmatrix.sync.aligned.m8n8.x4.shared.b16 {%0,%1,%2,%3}, [%4];"
                 : "=r"(r0), "=r"(r1), "=r"(r2), "=r"(r3) : "r"(addr));
}
__device__ __forceinline__ void mma16816(float* c, const unsigned* a, unsigned b0, unsigned b1) {
    asm volatile("mma.sync.aligned.m16n8k16.row.col.f32.f16.f16.f32 "
                 "{%0,%1,%2,%3}, {%4,%5,%6,%7}, {%8,%9}, {%0,%1,%2,%3};"
                 : "+f"(c[0]), "+f"(c[1]), "+f"(c[2]), "+f"(c[3])
                 : "r"(a[0]), "r"(a[1]), "r"(a[2]), "r"(a[3]), "r"(b0), "r"(b1));
}
__device__ __forceinline__ void cp16(unsigned dst, const void* src) {
    asm volatile("cp.async.cg.shared.global [%0], [%1], 16;" :: "r"(dst), "l"(src));
}

// ---------------- small kernels ----------------
__global__ void zero_kernel() {
    int i = threadIdx.x;
    if (i < EE) { g_counts[i] = 0; g_cursor[i] = 0; }
}
__global__ void offsets_kernel() {
    if (threadIdx.x == 0) {
        int s = 0;
        for (int e = 0; e < EE; ++e) { g_offsets[e] = s; s += g_counts[e]; }
    }
}
__global__ void scatter_kernel() {
    int t = blockIdx.x * blockDim.x + threadIdx.x;
    if (t >= TT) return;
    #pragma unroll
    for (int j = 0; j < TOPK; ++j) {
        int e = g_topk_idx[t*TOPK + j];
        int pos = g_offsets[e] + atomicAdd(&g_cursor[e], 1);
        g_pair_token[pos] = t;
        g_pair_pos[t*TOPK + j] = pos;
    }
}
__global__ __launch_bounds__(256) void convx_kernel(const float* __restrict__ x) {
    int i = blockIdx.x * 256 + threadIdx.x;
    g_xh[i] = __float2half_rn(x[i]);
}
// act = silu(C1)*C3 -> fp16
__global__ __launch_bounds__(256) void act_kernel() {
    size_t i4 = (size_t)blockIdx.x * 256 + threadIdx.x;
    float4 a = ((const float4*)g_C1)[i4];
    float4 b = ((const float4*)g_C3)[i4];
    float v0 = a.x / (1.f + expf(-a.x)) * b.x;
    float v1 = a.y / (1.f + expf(-a.y)) * b.y;
    float v2 = a.z / (1.f + expf(-a.z)) * b.z;
    float v3 = a.w / (1.f + expf(-a.w)) * b.w;
    unsigned h01, h23;
    cvt2h(h01, v1, v0);
    cvt2h(h23, v3, v2);
    ((uint2*)g_acth)[i4] = make_uint2(h01, h23);
}

// ---------------- gate + routing (proven) ----------------
__global__ __launch_bounds__(256) void gate_kernel(
        const float* __restrict__ x, const float* __restrict__ gw,
        const float* __restrict__ bias)
{
    __shared__ float xs[4][HH];
    __shared__ float logits_s[4][EE];
    __shared__ float bias_s[EE];
    int tid = threadIdx.x;
    int t0  = blockIdx.x * 4;
    const float4* xg  = (const float4*)(x + (size_t)t0 * HH);
    float4*       xs4 = (float4*)&xs[0][0];
    #pragma unroll
    for (int i = 0; i < 8; ++i) xs4[tid + i*256] = xg[tid + i*256];
    if (tid < EE) bias_s[tid] = bias[tid];
    __syncthreads();
    int warp = tid >> 5, lane = tid & 31;
    #pragma unroll
    for (int ei = 0; ei < 4; ++ei) {
        int e = warp*4 + ei;
        const float* gr = gw + (size_t)e * HH;
        float a0=0.f, a1=0.f, a2=0.f, a3=0.f;
        for (int h = lane; h < HH; h += 32) {
            float g = gr[h];
            a0 = fmaf(g, xs[0][h], a0); a1 = fmaf(g, xs[1][h], a1);
            a2 = fmaf(g, xs[2][h], a2); a3 = fmaf(g, xs[3][h], a3);
        }
        #pragma unroll
        for (int off = 16; off; off >>= 1) {
            a0 += __shfl_xor_sync(0xffffffffu, a0, off);
            a1 += __shfl_xor_sync(0xffffffffu, a1, off);
            a2 += __shfl_xor_sync(0xffffffffu, a2, off);
            a3 += __shfl_xor_sync(0xffffffffu, a3, off);
        }
        if (lane == 0) {
            logits_s[0][e] = a0; logits_s[1][e] = a1;
            logits_s[2][e] = a2; logits_s[3][e] = a3;
        }
    }
    __syncthreads();
    if (warp < 4) {
        int t = t0 + warp;
        float logit = logits_s[warp][lane];
        float s   = 1.f / (1.f + expf(-logit));
        float sfc = s + bias_s[lane];
        float m1 = sfc, m2 = -INFINITY;
        #pragma unroll
        for (int off = 4; off >= 1; off >>= 1) {
            float o1 = __shfl_xor_sync(0xffffffffu, m1, off);
            float o2 = __shfl_xor_sync(0xffffffffu, m2, off);
            float hi = fmaxf(m1, o1);
            float lo = fmaxf(fminf(m1, o1), fmaxf(m2, o2));
            m1 = hi; m2 = lo;
        }
        float gs = m1 + m2;
        float gv[4];
        gv[0] = __shfl_sync(0xffffffffu, gs, 0);
        gv[1] = __shfl_sync(0xffffffffu, gs, 8);
        gv[2] = __shfl_sync(0xffffffffu, gs, 16);
        gv[3] = __shfl_sync(0xffffffffu, gs, 24);
        int b1 = 0; float v1 = gv[0];
        #pragma unroll
        for (int gg = 1; gg < 4; ++gg) if (gv[gg] > v1) { v1 = gv[gg]; b1 = gg; }
        int b2 = -1; float v2 = -INFINITY;
        #pragma unroll
        for (int gg = 0; gg < 4; ++gg) {
            if (gg == b1) continue;
            if (gv[gg] > v2) { v2 = gv[gg]; b2 = gg; }
        }
        int mygrp = lane >> 3;
        float val = (mygrp == b1 || mygrp == b2) ? sfc : 0.0f;
        int sel_i[TOPK]; float sel_w[TOPK];
        float cur = val;
        #pragma unroll
        for (int j = 0; j < TOPK; ++j) {
            float bv = cur; int bi = lane;
            #pragma unroll
            for (int off = 16; off >= 1; off >>= 1) {
                float ov = __shfl_xor_sync(0xffffffffu, bv, off);
                int   oi = __shfl_xor_sync(0xffffffffu, bi, off);
                if (ov > bv || (ov == bv && oi < bi)) { bv = ov; bi = oi; }
            }
            sel_i[j] = bi;
            sel_w[j] = __shfl_sync(0xffffffffu, s, bi);
            if (lane == bi) cur = -INFINITY;
        }
        if (lane == 0) {
            float sum = sel_w[0] + sel_w[1] + sel_w[2] + sel_w[3];
            float scale = 2.5f / (sum + 1e-20f);
            #pragma unroll
            for (int j = 0; j < TOPK; ++j) {
                g_topk_idx[t*TOPK + j] = sel_i[j];
                g_topk_w[t*TOPK + j]   = sel_w[j] * scale;
                atomicAdd(&g_counts[sel_i[j]], 1);
            }
        }
    }
}

// ---------------- grouped single-term fp16 mma.sync GEMM ----------------
// C = fp16(A) @ fp16(W)^T, fp32 accum; W fp32 -> fp16 in-loader
__global__ void __launch_bounds__(256, 2) gemm_kernel(
    const __half* __restrict__ A, int lda,
    const float* __restrict__ Wra, const float* __restrict__ Wsa,
    const float* __restrict__ Wrb, const float* __restrict__ Wsb,
    int Kdim, int ybnd, float* __restrict__ Ca, float* __restrict__ Cb,
    int ldc, int gather)
{
    const int g     = blockIdx.z;
    const int mtile = blockIdx.x;
    const int y     = blockIdx.y;

    int m_count, base_pos;
    if (g < EE) { m_count = g_counts[g]; base_pos = g_offsets[g]; }
    else        { m_count = TT;          base_pos = NROUTED; }
    if (mtile * BM >= m_count) return;
    const int rows = min(BM, m_count - mtile * BM);

    const size_t wsz = (size_t)II * HH;
    const float* W;
    float* C;
    int n0;
    if (y < ybnd) {
        W = (g < EE) ? (Wra + (size_t)g * wsz) : Wsa;
        C = Ca; n0 = y * BN;
    } else {
        W = (g < EE) ? (Wrb + (size_t)g * wsz) : Wsb;
        C = Cb; n0 = (y - ybnd) * BN;
    }

    extern __shared__ char sm[];
    __shared__ int s_toks[BM];
    const unsigned smb = (unsigned)__cvta_generic_to_shared(sm);

    const int tid = threadIdx.x;
    if (tid < BM) {
        int r = min(tid, rows - 1);
        int pos = base_pos + mtile*BM + r;
        s_toks[tid] = gather ? ((g < EE) ? g_pair_token[pos] : (mtile*BM + r)) : pos;
    }
    __syncthreads();

    const int S = Kdim / BK;
    const int warp = tid >> 5, lane = tid & 31;
    const int wm = (warp & 1) * 64;
    const int wn = (warp >> 1) * 32;
    const int l15 = lane & 15, lh = lane >> 4;

    float acc[4][4][4];
    #pragma unroll
    for (int i = 0; i < 4; ++i)
        #pragma unroll
        for (int j = 0; j < 4; ++j)
            #pragma unroll
            for (int q = 0; q < 4; ++q) acc[i][j][q] = 0.f;

    // ---- preload stage 0 ----
    {
        #pragma unroll
        for (int t = 0; t < 2; ++t) {
            int c = tid + t*256;       // 0..511 : 128 rows x 4 chunks
            int row = c >> 2, ch = c & 3;
            const __half* src = A + (size_t)s_toks[row]*lda + ch*8;
            cp16(smb + OFF_A + row*ROWB + ch*16, src);
        }
        asm volatile("cp.async.commit_group;");
        float4 bv[4];
        #pragma unroll
        for (int t = 0; t < 4; ++t) {
            int c = tid + t*256;
            int row = c >> 3, f4 = c & 7;
            bv[t] = *(const float4*)(W + (size_t)(n0+row)*Kdim + f4*4);
        }
        #pragma unroll
        for (int t = 0; t < 4; ++t) {
            int c = tid + t*256;
            int row = c >> 3, f4 = c & 7;
            unsigned h01, h23;
            cvt2h(h01, bv[t].y, bv[t].x);
            cvt2h(h23, bv[t].w, bv[t].z);
            *(uint2*)(sm + OFF_B + row*ROWB + f4*8) = make_uint2(h01, h23);
        }
        asm volatile("cp.async.wait_group 0;" ::: "memory");
        __syncthreads();
    }

    int buf = 0;
    for (int s = 0; s < S; ++s) {
        const unsigned cb = smb + buf * BUFSZ;
        const unsigned nb = smb + (buf ^ 1) * BUFSZ;
        char* nbg = sm + (buf ^ 1) * BUFSZ;
        float4 bv[4];
        const int k0n = (s + 1) * BK;
        if (s + 1 < S) {
            #pragma unroll
            for (int t = 0; t < 4; ++t) {
                int c = tid + t*256;
                int row = c >> 3, f4 = c & 7;
                bv[t] = *(const float4*)(W + (size_t)(n0+row)*Kdim + k0n + f4*4);
            }
            #pragma unroll
            for (int t = 0; t < 2; ++t) {
                int c = tid + t*256;
                int row = c >> 2, ch = c & 3;
                const __half* src = A + (size_t)s_toks[row]*lda + k0n + ch*8;
                cp16(nb + OFF_A + row*ROWB + ch*16, src);
            }
            asm volatile("cp.async.commit_group;");
        }

        // ---- compute stage s: single term ----
        #pragma unroll
        for (int kk = 0; kk < BK; kk += 16) {
            unsigned bh[2][4];
            #pragma unroll
            for (int nf2 = 0; nf2 < 2; ++nf2) {
                unsigned addr = cb + OFF_B + (wn + nf2*16 + l15)*ROWB + (kk + lh*8)*2;
                ldsm4(bh[nf2][0], bh[nf2][1], bh[nf2][2], bh[nf2][3], addr);
            }
            #pragma unroll
            for (int mf = 0; mf < 4; ++mf) {
                unsigned ah[4];
                unsigned addr = cb + OFF_A + (wm + mf*16 + l15)*ROWB + (kk + lh*8)*2;
                ldsm4(ah[0], ah[1], ah[2], ah[3], addr);
                #pragma unroll
                for (int nf2 = 0; nf2 < 2; ++nf2) {
                    #pragma unroll
                    for (int u = 0; u < 2; ++u) {
                        mma16816(acc[mf][nf2*2 + u], ah, bh[nf2][u], bh[nf2][2 + u]);
                    }
                }
            }
        }

        if (s + 1 < S) {
            #pragma unroll
            for (int t = 0; t < 4; ++t) {
                int c = tid + t*256;
                int row = c >> 3, f4 = c & 7;
                unsigned h01, h23;
                cvt2h(h01, bv[t].y, bv[t].x);
                cvt2h(h23, bv[t].w, bv[t].z);
                *(uint2*)(nbg + OFF_B + row*ROWB + f4*8) = make_uint2(h01, h23);
            }
            asm volatile("cp.async.wait_group 0;" ::: "memory");
        }
        __syncthreads();
        buf ^= 1;
    }

    // ---- epilogue ----
    const int gq = lane >> 2, tau = lane & 3;
    #pragma unroll
    for (int mf = 0; mf < 4; ++mf) {
        #pragma unroll
        for (int nf = 0; nf < 4; ++nf) {
            int col = n0 + wn + nf*8 + tau*2;
            int r0 = wm + mf*16 + gq;
            int r1 = r0 + 8;
            if (r0 < rows) {
                float* d = C + (size_t)(base_pos + mtile*BM + r0) * ldc + col;
                d[0] = acc[mf][nf][0]; d[1] = acc[mf][nf][1];
            }
            if (r1 < rows) {
                float* d = C + (size_t)(base_pos + mtile*BM + r1) * ldc + col;
                d[0] = acc[mf][nf][2]; d[1] = acc[mf][nf][3];
            }
        }
    }
}

// ---------------- combine ----------------
__global__ __launch_bounds__(256) void combine_kernel(float* __restrict__ out)
{
    const int t = blockIdx.x;
    const int tid = threadIdx.x;
    __shared__ float w[TOPK];
    __shared__ int   pos[TOPK];
    if (tid < TOPK) {
        w[tid]   = g_topk_w[t*TOPK + tid];
        pos[tid] = g_pair_pos[t*TOPK + tid];
    }
    __syncthreads();
    const float4* sh = (const float4*)(g_pairout + (size_t)(NROUTED + t) * HH);
    const float4* p0 = (const float4*)(g_pairout + (size_t)pos[0] * HH);
    const float4* p1 = (const float4*)(g_pairout + (size_t)pos[1] * HH);
    const float4* p2 = (const float4*)(g_pairout + (size_t)pos[2] * HH);
    const float4* p3 = (const float4*)(g_pairout + (size_t)pos[3] * HH);
    float4* o = (float4*)(out + (size_t)t * HH);
    const float w0=w[0], w1=w[1], w2=w[2], w3=w[3];
    #pragma unroll
    for (int it = 0; it < HH/4/256; ++it) {
        int i = tid + it*256;
        float4 acc = sh[i];
        float4 v0 = p0[i], v1 = p1[i], v2 = p2[i], v3 = p3[i];
        acc.x += w0*v0.x + w1*v1.x + w2*v2.x + w3*v3.x;
        acc.y += w0*v0.y + w1*v1.y + w2*v2.y + w3*v3.y;
        acc.z += w0*v0.z + w1*v1.z + w2*v2.z + w3*v3.z;
        acc.w += w0*v0.w + w1*v1.w + w2*v2.w + w3*v3.w;
        o[i] = acc;
    }
}

// ---------------- launch ----------------
extern "C" void kernel_launch(void* const* d_in, const int* in_sizes, int n_in,
                              void* d_out, int out_size)
{
    const float* x    = (const float*)d_in[0];
    const float* gw   = (const float*)d_in[1];
    const float* bias = (const float*)d_in[2];
    const float* w1   = (const float*)d_in[3];
    const float* w3   = (const float*)d_in[4];
    const float* w2   = (const float*)d_in[5];
    const float* ws1  = (const float*)d_in[6];
    const float* ws3  = (const float*)d_in[7];
    const float* ws2  = (const float*)d_in[8];
    float* out = (float*)d_out;

    cudaFuncSetAttribute(gemm_kernel, cudaFuncAttributeMaxDynamicSharedMemorySize, SMEM_DYN);

    zero_kernel<<<1, 64>>>();
    gate_kernel<<<TT/4, 256>>>(x, gw, bias);
    offsets_kernel<<<1, 32>>>();
    scatter_kernel<<<TT/256, 256>>>();
    convx_kernel<<<TT*HH/256, 256>>>(x);

    __half *xh, *ah;
    cudaGetSymbolAddress((void**)&xh, g_xh);
    cudaGetSymbolAddress((void**)&ah, g_acth);
    float *c1, *c3, *po;
    cudaGetSymbolAddress((void**)&c1, g_C1);
    cudaGetSymbolAddress((void**)&c3, g_C3);
    cudaGetSymbolAddress((void**)&po, g_pairout);

    // phase A: C1 = X@W1^T (y<8), C3 = X@W3^T (y>=8); K=HH
    gemm_kernel<<<dim3(16, 16, EE+1), 256, SMEM_DYN>>>(
        xh, HH, w1, ws1, w3, ws3, HH, 8, c1, c3, II, 1);
    act_kernel<<<(int)((size_t)NPAIRS*II/4/256), 256>>>();
    // phase B: pairout = act@W2^T; K=II
    gemm_kernel<<<dim3(16, 16, EE+1), 256, SMEM_DYN>>>(
        ah, II, w2, ws2, w2, ws2, II, 16, po, po, HH, 0);
    combine_kernel<<<TT, 256>>>(out);
}